// round 15
// baseline (speedup 1.0000x reference)
#include <cuda_runtime.h>
#include <cuda_bf16.h>
#include <cuda_fp16.h>
#include <cstdint>
#include <cstddef>

#define Sq 1024
#define Dm 768
#define Hh 12
#define HDm 64
#define Bb 8
#define Tt 384
#define SCALE_L2E 0.18033688011112042f   /* 0.125 * log2(e) */

// ---------------- scratch (device globals; no allocation allowed) ----------
__device__ float g_T[3][Bb][Dm];                    // time q/k/v vectors
__device__ float g_TQC[Bb * Hh][Sq];                // SCALE*tq.Er[t] per (b,h)
__device__ __half g_P16[(size_t)Bb * Sq * Dm];      // patches fp16
__device__ __half g_WT16[3][Dm][Dm];                // W^T fp16 [z][n][k]
__device__ __half g_Q16[(size_t)Bb * Sq * Dm];      // (qs+tq)*0.125*log2e (fp16)
__device__ __half g_K16[(size_t)Bb * Sq * Dm];      // ks+tk  (fp16)
__device__ __half g_V16[(size_t)Bb * Sq * Dm];      // vs+tv  (fp16)
__device__ __half g_Er16[Sq][HDm];

// ---------------- PTX helpers (baseline ISA: sm_80+) ------------------------
__device__ __forceinline__ uint32_t smem_u32(const void* p) {
    uint32_t a;
    asm("{ .reg .u64 t; cvta.to.shared.u64 t, %1; cvt.u32.u64 %0, t; }"
        : "=r"(a) : "l"(p));
    return a;
}
__device__ __forceinline__ void ldmx4(uint32_t* r, uint32_t addr) {
    asm volatile("ldmatrix.sync.aligned.m8n8.x4.shared.b16 {%0,%1,%2,%3}, [%4];"
                 : "=r"(r[0]), "=r"(r[1]), "=r"(r[2]), "=r"(r[3]) : "r"(addr));
}
__device__ __forceinline__ void ldmx4t(uint32_t* r, uint32_t addr) {
    asm volatile("ldmatrix.sync.aligned.m8n8.x4.trans.shared.b16 {%0,%1,%2,%3}, [%4];"
                 : "=r"(r[0]), "=r"(r[1]), "=r"(r[2]), "=r"(r[3]) : "r"(addr));
}
__device__ __forceinline__ void mma16816h(float* c, const uint32_t* a, const uint32_t* b) {
    asm volatile(
        "mma.sync.aligned.m16n8k16.row.col.f32.f16.f16.f32 "
        "{%0,%1,%2,%3}, {%4,%5,%6,%7}, {%8,%9}, {%0,%1,%2,%3};"
        : "+f"(c[0]), "+f"(c[1]), "+f"(c[2]), "+f"(c[3])
        : "r"(a[0]), "r"(a[1]), "r"(a[2]), "r"(a[3]), "r"(b[0]), "r"(b[1]));
}
__device__ __forceinline__ float ex2f(float x) {
    float y; asm("ex2.approx.f32 %0, %1;" : "=f"(y) : "f"(x)); return y;
}
#define CP16(dst, src) asm volatile("cp.async.cg.shared.global [%0], [%1], 16;" :: "r"(dst), "l"(src))
#define CP4(dst, src)  asm volatile("cp.async.ca.shared.global [%0], [%1], 4;" :: "r"(dst), "l"(src))
#define CP_COMMIT()    asm volatile("cp.async.commit_group;" ::: "memory")
#define CP_WAIT1()     asm volatile("cp.async.wait_group 1;" ::: "memory")
#define CP_WAIT0()     asm volatile("cp.async.wait_group 0;" ::: "memory")

#define KC 64
#define RSTR 72
#define TILE_B (128 * RSTR * 2)          // 18432 B per 128-row fp16 tile
#define STAGE2_B (2 * TILE_B)            // A, B = 36864 B (qkv single-pass)
#define DSTR 132

__device__ __forceinline__ uint32_t packh2(float x, float y) {
    __half2 hh = __floats2half2_rn(x, y);
    return *(uint32_t*)&hh;
}

// ---------------- kernel 1: time projections (parallelized) ----------------
__global__ void __launch_bounds__(128) time_proj(
    const float* __restrict__ time_emb,
    const float* __restrict__ Wqt, const float* __restrict__ bqt,
    const float* __restrict__ Wkt, const float* __restrict__ bkt,
    const float* __restrict__ Wvt, const float* __restrict__ bvt)
{
    const int b = blockIdx.y;
    const int n = blockIdx.x * 128 + threadIdx.x;
    __shared__ float te[Tt];
    for (int i = threadIdx.x; i < Tt; i += 128)
        te[i] = time_emb[b * Tt + i];
    __syncthreads();
    float aq = 0.f, ak = 0.f, av = 0.f;
    for (int t = 0; t < Tt; t++) {
        float x = te[t];
        aq += x * Wqt[t * Dm + n];
        ak += x * Wkt[t * Dm + n];
        av += x * Wvt[t * Dm + n];
    }
    g_T[0][b][n] = aq + bqt[n];
    g_T[1][b][n] = ak + bkt[n];
    g_T[2][b][n] = av + bvt[n];
}

// ---------------- kernel 1b: TQC[b*Hh+h][t] = SCALE * tq(b,h) . Er[t] ------
__global__ void __launch_bounds__(256) tqc_kernel(const float* __restrict__ Er)
{
    const int bh = blockIdx.x;
    const int b = bh / Hh, h = bh % Hh;
    __shared__ float tq[HDm];
    if (threadIdx.x < HDm)
        tq[threadIdx.x] = g_T[0][b][h * HDm + threadIdx.x];
    __syncthreads();
    for (int t = threadIdx.x; t < Sq; t += 256) {
        const float* er = Er + (size_t)t * HDm;
        float s = 0.f;
        #pragma unroll 16
        for (int d = 0; d < HDm; d++)
            s += tq[d] * er[d];
        g_TQC[bh][t] = s * SCALE_L2E;
    }
}

// ---------------- kernel 2: fused preps (patches | er | wt) ----------------
// blocks [0,6144): patches; [6144,6208): er; [6208,7936): wt
__global__ void __launch_bounds__(256) prep_all(
    const float* __restrict__ patches, const float* __restrict__ Er,
    const float* __restrict__ Wq, const float* __restrict__ Wk,
    const float* __restrict__ Wv)
{
    const int bid = blockIdx.x;
    if (bid < 6144) {
        size_t i = (size_t)bid * 256 + threadIdx.x;
        float4 v = ((const float4*)patches)[i];
        uint32_t* H = (uint32_t*)g_P16;
        H[2 * i] = packh2(v.x, v.y);
        H[2 * i + 1] = packh2(v.z, v.w);
    } else if (bid < 6208) {
        size_t i = (size_t)(bid - 6144) * 256 + threadIdx.x;
        float4 v = ((const float4*)Er)[i];
        uint32_t* E = (uint32_t*)&g_Er16[0][0];
        E[2 * i] = packh2(v.x, v.y);
        E[2 * i + 1] = packh2(v.z, v.w);
    } else {
        const int w = bid - 6208;
        const int z = w / 576;
        const int rem = w % 576;
        const int n0 = (rem % 24) * 32, k0 = (rem / 24) * 32;
        const float* __restrict__ W = (z == 0) ? Wq : (z == 1 ? Wk : Wv);
        __shared__ float s[32][33];
        const int tx = threadIdx.x & 31, ty = threadIdx.x >> 5;
        #pragma unroll
        for (int i = 0; i < 4; i++)
            s[ty + 8 * i][tx] = W[(size_t)(k0 + ty + 8 * i) * Dm + n0 + tx];
        __syncthreads();
        #pragma unroll
        for (int i = 0; i < 4; i++) {
            int n = n0 + ty + 8 * i, k = k0 + tx;
            g_WT16[z][n][k] = __float2half_rn(s[tx][ty + 8 * i]);
        }
    }
}

// ---------------- microkernel: one Kc=64 chunk, single-pass fp16 -----------
__device__ __forceinline__ void mma_chunk1(uint32_t stage_base, int wm, int wn,
                                           int lane, float c[4][4][4])
{
    const uint32_t aRow = (uint32_t)(wm * 64 + (lane & 15));
    const uint32_t aColBase = (uint32_t)((lane >> 4) * 8);
    const uint32_t bRow = (uint32_t)(wn * 32 + ((lane >> 3) & 1) * 8 + (lane & 7));
    const uint32_t sA = stage_base;
    const uint32_t sB = stage_base + TILE_B;

    #pragma unroll
    for (int ks = 0; ks < 4; ks++) {
        const uint32_t kcol = (uint32_t)(ks * 16) + aColBase;
        uint32_t aa[4][4], bb[4][2];
        #pragma unroll
        for (int mt = 0; mt < 4; mt++) {
            uint32_t off = ((aRow + mt * 16) * RSTR + kcol) * 2;
            ldmx4(aa[mt], sA + off);
        }
        #pragma unroll
        for (int nt2 = 0; nt2 < 2; nt2++) {
            uint32_t off = ((bRow + nt2 * 16) * RSTR + kcol) * 2;
            uint32_t t[4];
            ldmx4(t, sB + off);
            bb[nt2 * 2][0] = t[0]; bb[nt2 * 2][1] = t[2];
            bb[nt2 * 2 + 1][0] = t[1]; bb[nt2 * 2 + 1][1] = t[3];
        }
        #pragma unroll
        for (int mt = 0; mt < 4; mt++)
            #pragma unroll
            for (int nt = 0; nt < 4; nt++)
                mma16816h(c[mt][nt], aa[mt], bb[nt]);
    }
}

// ---------------- kernel 3: QKV via mma.sync fp16 (3-stage, 2 CTA/SM) ------
__global__ void __launch_bounds__(256, 2) qkv_mma(
    const float* __restrict__ bq, const float* __restrict__ bk,
    const float* __restrict__ bv)
{
    extern __shared__ char sm[];
    const uint32_t smb = smem_u32(sm);
    const int z = blockIdx.z;
    const int n0 = blockIdx.x * 128, m0 = blockIdx.y * 128;
    const int tid = threadIdx.x;
    const int warp = tid >> 5, lane = tid & 31;
    const int wm = warp & 1, wn = warp >> 1;

    auto load_stage = [&](int chunk, int s) {
        const uint32_t st = smb + (uint32_t)s * STAGE2_B;
        const int k0 = chunk * KC;
        #pragma unroll
        for (int it = 0; it < 4; it++) {
            int i = tid + it * 256;
            int r = i >> 3, cc = i & 7;
            uint32_t doff = (uint32_t)(r * RSTR + cc * 8) * 2;
            CP16(st + doff, g_P16 + (size_t)(m0 + r) * Dm + k0 + cc * 8);
            CP16(st + TILE_B + doff, &g_WT16[z][n0 + r][k0 + cc * 8]);
        }
        CP_COMMIT();
    };

    float c[4][4][4] = {};

    load_stage(0, 0);
    load_stage(1, 1);
    for (int ch = 0; ch < 12; ch++) {
        if (ch < 10) CP_WAIT1(); else CP_WAIT0();
        __syncthreads();
        if (ch + 2 < 12) load_stage(ch + 2, (ch + 2) % 3);
        mma_chunk1(smb + (uint32_t)(ch % 3) * STAGE2_B, wm, wn, lane, c);
    }

    const float* bias = (z == 0) ? bq : (z == 1 ? bk : bv);
    const int lrow = lane >> 2, lcol = (lane & 3) * 2;
    #pragma unroll
    for (int mt = 0; mt < 4; mt++) {
        #pragma unroll
        for (int nt = 0; nt < 4; nt++) {
            const int col = n0 + wn * 32 + nt * 8 + lcol;
            const float bx = bias[col], by = bias[col + 1];
            #pragma unroll
            for (int hf = 0; hf < 2; hf++) {
                const int row = m0 + wm * 64 + mt * 16 + lrow + hf * 8;
                const int b = row >> 10;
                const float v0 = c[mt][nt][hf * 2 + 0] + bx;
                const float v1 = c[mt][nt][hf * 2 + 1] + by;
                const float t0 = g_T[z][b][col];
                const float t1 = g_T[z][b][col + 1];
                const size_t o = (size_t)row * Dm + col;
                if (z == 0) {
                    *(uint32_t*)&g_Q16[o] = packh2((v0 + t0) * SCALE_L2E,
                                                   (v1 + t1) * SCALE_L2E);
                } else if (z == 1) {
                    *(uint32_t*)&g_K16[o] = packh2(v0 + t0, v1 + t1);
                } else {
                    *(uint32_t*)&g_V16[o] = packh2(v0 + t0, v1 + t1);
                }
            }
        }
    }
}

// ---------------- kernel 4: fused flash attention + rel-bias (fp16) --------
// 256 threads (8 warps), 2 CTAs/SM. Diagonal bias layout, log2 softmax.
// D strips now use the (80-row) Q tile; bias = Q.Er[t(e)] - TQC[bh][t(e)],
// with the TQC scalar subtracted at Dd-store time (tqc ring parallel to Er).
#define aQ    0u            /* 80x72 fp16 = 11520 */
#define aKV   11520u        /* stage: K16 | V16 each 9216 = 18432; x2 */
#define aEr   48384u        /* 192x72 fp16 = 27648 */
#define aTq   76032u        /* 192 f32 = 768 */
#define aD    76800u        /* 64x132 fp16 = 16896 */
#define aRed  93696u        /* sM 128 f32 + sL 128 f32 */
#define ATTN_SMEM 94720
#define OSTR 68

__global__ void __launch_bounds__(256, 2) attn_mma(float* __restrict__ out)
{
    extern __shared__ char sm[];
    const uint32_t smb = smem_u32(sm);
    const int bx = blockIdx.x;
    const int q0 = bx * 64;
    const int h = blockIdx.y, b = blockIdx.z;
    const int tid = threadIdx.x, warp = tid >> 5, lane = tid & 31;
    const int wp = warp & 3, wh = warp >> 2;
    __half* Dd = (__half*)(sm + aD);
    float* sTq = (float*)(sm + aTq);
    float* sM = (float*)(sm + aRed);
    float* sL = sM + 128;
    const float* __restrict__ tqcg = g_TQC[b * Hh + h];

    auto load_kv = [&](int kt, int s) {
        const uint32_t st = smb + aKV + (uint32_t)s * 18432u;
        const size_t krow0 = ((size_t)(b * Sq + kt * 64)) * Dm + h * HDm;
        #pragma unroll
        for (int it = 0; it < 2; it++) {
            int i = tid + it * 256;
            int r = i >> 3, cc = i & 7;
            uint32_t doff = (uint32_t)(r * RSTR + cc * 8) * 2;
            size_t src = krow0 + (size_t)r * Dm + cc * 8;
            CP16(st + doff, g_K16 + src);
            CP16(st + 9216u + doff, g_V16 + src);
        }
    };
    auto load_er = [&](int s) {
        const int estart = s * 64 - q0;
        const int slot = ((s + 3) % 3) * 64;
        #pragma unroll
        for (int it = 0; it < 2; it++) {
            int i = tid + it * 256;
            int r = i >> 3, cc = i & 7;
            int e = estart + r;
            int t = (e <= 0) ? (Sq - 1 + e) : (e - 2);
            if (t < 0) t = 0; if (t > Sq - 1) t = Sq - 1;
            uint32_t doff = (uint32_t)((slot + r) * RSTR + cc * 8) * 2;
            CP16(smb + aEr + doff, &g_Er16[t][cc * 8]);
            if (cc == 0)
                CP4(smb + aTq + (uint32_t)(slot + r) * 4, &tqcg[t]);
        }
    };
    // mixed strip (contains e=1): per-row shift + zeroing; A = Q tile rows
    auto do_dstrip_m = [&](int s) {
        const int base = s * 64 - q0;
        const uint32_t erow0 = (uint32_t)(((s + 3) % 3) * 64);
        const int slot = ((s + 3) % 3) * 64;
        const int par = warp & 1;
        uint32_t eb[4][2];
        const uint32_t nrow = erow0 +
            (uint32_t)((warp & 6) * 8 + ((lane >> 3) & 1) * 8 + (lane & 7));
        #pragma unroll
        for (int ks = 0; ks < 4; ks++) {
            uint32_t addr = smb + aEr +
                (nrow * RSTR + (uint32_t)(ks * 16 + (lane >> 4) * 8)) * 2;
            uint32_t t4[4];
            ldmx4(t4, addr);
            eb[ks][0] = t4[par]; eb[ks][1] = t4[2 + par];
        }
        const int e0l = warp * 8 + (lane & 3) * 2;     // local e (even)
        const int e0 = base + e0l;
        const float tq0 = sTq[slot + e0l];
        const float tq1 = sTq[slot + e0l + 1];
        #pragma unroll
        for (int mt = 0; mt < 5; mt++) {
            uint32_t sa[4][4];
            const uint32_t arow = (uint32_t)(mt * 16 + (lane & 15));
            #pragma unroll
            for (int ks = 0; ks < 4; ks++) {
                uint32_t addr = smb + aQ +
                    (arow * RSTR + (uint32_t)(ks * 16 + (lane >> 4) * 8)) * 2;
                ldmx4(sa[ks], addr);
            }
            float cc4[4] = {};
            #pragma unroll
            for (int ks = 0; ks < 4; ks++)
                mma16816h(cc4, sa[ks], eb[ks]);
            const int p = (e0 >= 2) ? 1 : 0;
            #pragma unroll
            for (int rr = 0; rr < 2; rr++) {
                const int r = mt * 16 + (lane >> 2) + rr * 8;
                const int q_dst = r - p;
                if (q_dst >= 0 && q_dst < 64) {
                    const int j0 = (e0 + q_dst) & 127;
                    const int j1 = (e0 + 1 + q_dst) & 127;
                    Dd[q_dst * DSTR + j0] = __float2half_rn(cc4[rr * 2] - tq0);
                    Dd[q_dst * DSTR + j1] =
                        (e0 + 1 == 1) ? __float2half_rn(0.f)
                                      : __float2half_rn(cc4[rr * 2 + 1] - tq1);
                }
            }
        }
    };
    // uniform strip: O[e][q] = Er_strip x Q(rows q+p); subtract tqc at store
    auto do_dstrip_u = [&](int s, int p) {
        const uint32_t erow0 = (uint32_t)(((s + 3) % 3) * 64);
        const int slot = ((s + 3) % 3) * 64;
        const int estart = s * 64 - q0;
        uint32_t ea[4][4];
        {
            const uint32_t arow = erow0 + (uint32_t)(wp * 16 + (lane & 15));
            #pragma unroll
            for (int ks = 0; ks < 4; ks++) {
                uint32_t addr = smb + aEr +
                    (arow * RSTR + (uint32_t)(ks * 16 + (lane >> 4) * 8)) * 2;
                ldmx4(ea[ks], addr);
            }
        }
        float c4[4][4] = {};
        #pragma unroll
        for (int ks = 0; ks < 4; ks++) {
            uint32_t bb[4][2];
            #pragma unroll
            for (int pp = 0; pp < 2; pp++) {
                uint32_t nrow = (uint32_t)(p + wh * 32 + pp * 16 +
                                ((lane >> 3) & 1) * 8 + (lane & 7));
                uint32_t addr = smb + aQ +
                    (nrow * RSTR + (uint32_t)(ks * 16 + (lane >> 4) * 8)) * 2;
                uint32_t t4[4];
                ldmx4(t4, addr);
                bb[pp * 2][0] = t4[0]; bb[pp * 2][1] = t4[2];
                bb[pp * 2 + 1][0] = t4[1]; bb[pp * 2 + 1][1] = t4[3];
            }
            #pragma unroll
            for (int nt = 0; nt < 4; nt++)
                mma16816h(c4[nt], ea[ks], bb[nt]);
        }
        #pragma unroll
        for (int hf = 0; hf < 2; hf++) {
            const int e_loc = wp * 16 + (lane >> 2) + hf * 8;
            const int e_abs = estart + e_loc;
            const float tqv = sTq[slot + e_loc];
            #pragma unroll
            for (int nt = 0; nt < 4; nt++) {
                const int qb = wh * 32 + nt * 8 + (lane & 3) * 2;
                Dd[qb * DSTR + ((e_abs + qb) & 127)] =
                    __float2half_rn(c4[nt][hf * 2] - tqv);
                Dd[(qb + 1) * DSTR + ((e_abs + qb + 1) & 127)] =
                    __float2half_rn(c4[nt][hf * 2 + 1] - tqv);
            }
        }
    };
    auto dstrip = [&](int s) {
        if (s == bx) do_dstrip_m(s);
        else do_dstrip_u(s, (s > bx) ? 1 : 0);
    };

    // ---- prologue loads: G0 = {Q(80), er(-1,0,1), kv0}, G1 = {kv1} --------
    {
        const size_t qrow0 = ((size_t)(b * Sq + q0)) * Dm + h * HDm;
        #pragma unroll
        for (int it = 0; it < 3; it++) {
            int i = tid + it * 256;
            if (i < 640) {
                int r = i >> 3, cc = i & 7;
                int rr = q0 + r; if (rr > Sq - 1) rr = Sq - 1;
                uint32_t doff = (uint32_t)(r * RSTR + cc * 8) * 2;
                CP16(smb + aQ + doff,
                     g_Q16 + ((size_t)(b * Sq + rr)) * Dm + h * HDm + cc * 8);
            }
        }
        (void)qrow0;
        load_er(-1); load_er(0); load_er(1);
        load_kv(0, 0);
        CP_COMMIT();                 // G0
        load_kv(1, 1);
        CP_COMMIT();                 // G1
    }

    CP_WAIT1();
    __syncthreads();                 // G0 visible (Q, er/tqc(-1,0,1), kv0)

    // ---- hoist Q fragments (loop-invariant, rows 0..63) ----
    uint32_t qa[4][4];
    {
        const uint32_t arow = (uint32_t)(wp * 16 + (lane & 15));
        #pragma unroll
        for (int ks = 0; ks < 4; ks++) {
            uint32_t addr = smb + aQ +
                (arow * RSTR + (uint32_t)(ks * 16 + (lane >> 4) * 8)) * 2;
            ldmx4(qa[ks], addr);
        }
    }

    // ---- prologue D strips {-1, 0} ----
    dstrip(-1);
    dstrip(0);
    __syncthreads();                 // Dd + all prologue dstrip reads done

    float m_[2] = {-1e30f, -1e30f}, l_[2] = {0.f, 0.f};
    float co[8][4] = {};
    const int row16 = (lane >> 2);

    for (int kt = 0; kt < 16; kt++) {
        const int s = kt & 1;
        const int d0 = kt * 64 - q0;
        if (kt > 0) { CP_WAIT1(); __syncthreads(); }  // KV(kt), Er(kt+1), Dd(kt)

        // ---- QK^T ----
        float c[4][4] = {};
        {
            const uint32_t stK = smb + aKV + (uint32_t)s * 18432u;
            #pragma unroll
            for (int ks = 0; ks < 4; ks++) {
                uint32_t bh[4][2];
                #pragma unroll
                for (int pp = 0; pp < 2; pp++) {
                    uint32_t nrow = (uint32_t)(wh * 32 + pp * 16 +
                                    ((lane >> 3) & 1) * 8 + (lane & 7));
                    uint32_t addr = stK +
                        (nrow * RSTR + (uint32_t)(ks * 16 + (lane >> 4) * 8)) * 2;
                    uint32_t t4[4];
                    ldmx4(t4, addr);
                    bh[pp * 2][0] = t4[0]; bh[pp * 2][1] = t4[2];
                    bh[pp * 2 + 1][0] = t4[1]; bh[pp * 2 + 1][1] = t4[3];
                }
                #pragma unroll
                for (int nt = 0; nt < 4; nt++)
                    mma16816h(c[nt], qa[ks], bh[nt]);
            }
        }

        // ---- bias add (diagonal) + log2 softmax ----
        float mloc[2] = {-1e30f, -1e30f};
        #pragma unroll
        for (int hf = 0; hf < 2; hf++) {
            const int q_loc = wp * 16 + row16 + hf * 8;
            const uint32_t rbase = (uint32_t)(q_loc * DSTR);
            #pragma unroll
            for (int nt = 0; nt < 4; nt++) {
                const int col = wh * 32 + nt * 8 + (lane & 3) * 2;
                const int idx = (d0 + col) & 127;        // even -> aligned
                __half2 b2 = *(__half2*)&Dd[rbase + idx];
                float2 bf = __half22float2(b2);
                float sv0 = c[nt][hf * 2 + 0] + bf.x;
                float sv1 = c[nt][hf * 2 + 1] + bf.y;
                c[nt][hf * 2 + 0] = sv0;
                c[nt][hf * 2 + 1] = sv1;
                mloc[hf] = fmaxf(mloc[hf], fmaxf(sv0, sv1));
            }
        }
        float corr[2], psum[2] = {0.f, 0.f};
        #pragma unroll
        for (int hf = 0; hf < 2; hf++) {
            mloc[hf] = fmaxf(mloc[hf], __shfl_xor_sync(0xffffffffu, mloc[hf], 1));
            mloc[hf] = fmaxf(mloc[hf], __shfl_xor_sync(0xffffffffu, mloc[hf], 2));
            float mn = fmaxf(m_[hf], mloc[hf]);
            corr[hf] = ex2f(m_[hf] - mn);
            m_[hf] = mn;
        }
        #pragma unroll
        for (int nt = 0; nt < 4; nt++) {
            #pragma unroll
            for (int k4 = 0; k4 < 4; k4++) {
                const int hf = k4 >> 1;
                float p = ex2f(c[nt][k4] - m_[hf]);
                c[nt][k4] = p;
                psum[hf] += p;
            }
        }
        #pragma unroll
        for (int hf = 0; hf < 2; hf++) {
            psum[hf] += __shfl_xor_sync(0xffffffffu, psum[hf], 1);
            psum[hf] += __shfl_xor_sync(0xffffffffu, psum[hf], 2);
            l_[hf] = l_[hf] * corr[hf] + psum[hf];
        }
        #pragma unroll
        for (int nt = 0; nt < 8; nt++) {
            co[nt][0] *= corr[0]; co[nt][1] *= corr[0];
            co[nt][2] *= corr[1]; co[nt][3] *= corr[1];
        }

        // ---- PV ----
        {
            const uint32_t stV = smb + aKV + (uint32_t)s * 18432u + 9216u;
            #pragma unroll
            for (int ktk = 0; ktk < 2; ktk++) {
                uint32_t pha[4];
                #pragma unroll
                for (int sub = 0; sub < 2; sub++)
                    #pragma unroll
                    for (int h2 = 0; h2 < 2; h2++)
                        pha[h2 + sub * 2] = packh2(c[2 * ktk + sub][h2 * 2],
                                                   c[2 * ktk + sub][h2 * 2 + 1]);
                uint32_t vb[8][2];
                #pragma unroll
                for (int pp = 0; pp < 4; pp++) {
                    uint32_t krow = (uint32_t)(wh * 32 + ktk * 16 +
                                   (lane & 7) + ((lane >> 3) & 1) * 8);
                    uint32_t ncol = (uint32_t)(pp * 16 + (lane >> 4) * 8);
                    uint32_t addr = stV + (krow * RSTR + ncol) * 2;
                    uint32_t t4[4];
                    ldmx4t(t4, addr);
                    vb[pp * 2][0] = t4[0]; vb[pp * 2][1] = t4[1];
                    vb[pp * 2 + 1][0] = t4[2]; vb[pp * 2 + 1][1] = t4[3];
                }
                #pragma unroll
                for (int nt = 0; nt < 8; nt++)
                    mma16816h(co[nt], pha, vb[nt]);
            }
        }

        __syncthreads();   // ALL bias(kt)+PV(kt) reads done before dstrip/loads

        // ---- D strip kt+1 ----
        if (kt + 1 <= 15) dstrip(kt + 1);

        if (kt + 2 < 16) load_kv(kt + 2, s);
        if (kt + 2 == 2) load_er(2);    // slot 2 free after prologue dstrips
        if (kt + 3 <= 15) load_er(kt + 3);
        CP_COMMIT();
    }

    // ---- merge the two k-half softmax states, write out ----
    if ((lane & 3) == 0) {
        #pragma unroll
        for (int hf = 0; hf < 2; hf++) {
            sM[wh * 64 + wp * 16 + row16 + hf * 8] = m_[hf];
            sL[wh * 64 + wp * 16 + row16 + hf * 8] = l_[hf];
        }
    }
    __syncthreads();
    float myc[2], inv[2];
    #pragma unroll
    for (int hf = 0; hf < 2; hf++) {
        const int rowi = wp * 16 + row16 + hf * 8;
        float mo = sM[(wh ^ 1) * 64 + rowi];
        float lo2 = sL[(wh ^ 1) * 64 + rowi];
        float mstar = fmaxf(m_[hf], mo);
        myc[hf] = ex2f(m_[hf] - mstar);
        float otc = ex2f(mo - mstar);
        inv[hf] = 1.0f / (l_[hf] * myc[hf] + lo2 * otc);
    }
    __syncthreads();
    float* sOut = (float*)(sm + aKV);
    if (wh == 1) {
        #pragma unroll
        for (int hf = 0; hf < 2; hf++) {
            const int row = wp * 16 + row16 + hf * 8;
            #pragma unroll
            for (int nt = 0; nt < 8; nt++) {
                const int col = nt * 8 + (lane & 3) * 2;
                *(float2*)&sOut[row * OSTR + col] =
                    make_float2(co[nt][hf * 2] * myc[hf],
                                co[nt][hf * 2 + 1] * myc[hf]);
            }
        }
    }
    __syncthreads();
    if (wh == 0) {
        #pragma unroll
        for (int hf = 0; hf < 2; hf++) {
            const int row = wp * 16 + row16 + hf * 8;
            const size_t ob = ((size_t)(b * Sq + q0 + row)) * Dm + h * HDm;
            #pragma unroll
            for (int nt = 0; nt < 8; nt++) {
                const int col = nt * 8 + (lane & 3) * 2;
                float2 pr = *(float2*)&sOut[row * OSTR + col];
                *(float2*)&out[ob + col] =
                    make_float2((co[nt][hf * 2] * myc[hf] + pr.x) * inv[hf],
                                (co[nt][hf * 2 + 1] * myc[hf] + pr.y) * inv[hf]);
            }
        }
    }
}

// ---------------- launch ----------------------------------------------------
extern "C" void kernel_launch(void* const* d_in, const int* in_sizes, int n_in,
                              void* d_out, int out_size)
{
    (void)in_sizes; (void)n_in; (void)out_size;
    const float* patches  = (const float*)d_in[0];
    const float* time_emb = (const float*)d_in[1];
    const float* Wqs = (const float*)d_in[2];
    const float* bqs = (const float*)d_in[3];
    const float* Wks = (const float*)d_in[4];
    const float* bks = (const float*)d_in[5];
    const float* Wvs = (const float*)d_in[6];
    const float* bvs = (const float*)d_in[7];
    const float* Wqt = (const float*)d_in[8];
    const float* bqt = (const float*)d_in[9];
    const float* Wkt = (const float*)d_in[10];
    const float* bkt = (const float*)d_in[11];
    const float* Wvt = (const float*)d_in[12];
    const float* bvt = (const float*)d_in[13];
    const float* Er  = (const float*)d_in[14];
    float* out = (float*)d_out;

    time_proj<<<dim3(Dm / 128, Bb), 128>>>(time_emb, Wqt, bqt, Wkt, bkt, Wvt, bvt);
    prep_all<<<7936, 256>>>(patches, Er, Wqs, Wks, Wvs);
    tqc_kernel<<<Bb * Hh, 256>>>(Er);

    const int qkv_smem = 3 * STAGE2_B;  // 110592 -> 2 CTAs/SM
    cudaFuncSetAttribute(qkv_mma, cudaFuncAttributeMaxDynamicSharedMemorySize, qkv_smem);
    qkv_mma<<<dim3(Dm / 128, (Bb * Sq) / 128, 3), 256, qkv_smem>>>(bqs, bks, bvs);

    cudaFuncSetAttribute(attn_mma, cudaFuncAttributeMaxDynamicSharedMemorySize, ATTN_SMEM);
    attn_mma<<<dim3(Sq / 64, Hh, Bb), 256, ATTN_SMEM>>>(out);
}

// round 16
// speedup vs baseline: 1.1205x; 1.1205x over previous
#include <cuda_runtime.h>
#include <cuda_bf16.h>
#include <cuda_fp16.h>
#include <cstdint>
#include <cstddef>

#define Sq 1024
#define Dm 768
#define Hh 12
#define HDm 64
#define Bb 8
#define Tt 384
#define SCALE_L2E 0.18033688011112042f   /* 0.125 * log2(e) */

// ---------------- scratch (device globals; no allocation allowed) ----------
__device__ float g_T[3][Bb][Dm];                    // time q/k/v vectors
__device__ __half g_P16[(size_t)Bb * Sq * Dm];      // patches fp16
__device__ __half g_WT16[3][Dm][Dm];                // W^T fp16 [z][n][k]
__device__ __half g_Q16[(size_t)Bb * Sq * Dm];      // (qs+tq)*0.125*log2e (fp16)
__device__ __half g_K16[(size_t)Bb * Sq * Dm];      // ks+tk  (fp16)
__device__ __half g_QS16[(size_t)Bb * Sq * Dm];     // qs*0.125*log2e (fp16)
__device__ __half g_V16[(size_t)Bb * Sq * Dm];      // vs+tv  (fp16)
__device__ __half g_Er16[Sq][HDm];

// ---------------- PTX helpers (baseline ISA: sm_80+) ------------------------
__device__ __forceinline__ uint32_t smem_u32(const void* p) {
    uint32_t a;
    asm("{ .reg .u64 t; cvta.to.shared.u64 t, %1; cvt.u32.u64 %0, t; }"
        : "=r"(a) : "l"(p));
    return a;
}
__device__ __forceinline__ void ldmx4(uint32_t* r, uint32_t addr) {
    asm volatile("ldmatrix.sync.aligned.m8n8.x4.shared.b16 {%0,%1,%2,%3}, [%4];"
                 : "=r"(r[0]), "=r"(r[1]), "=r"(r[2]), "=r"(r[3]) : "r"(addr));
}
__device__ __forceinline__ void ldmx4t(uint32_t* r, uint32_t addr) {
    asm volatile("ldmatrix.sync.aligned.m8n8.x4.trans.shared.b16 {%0,%1,%2,%3}, [%4];"
                 : "=r"(r[0]), "=r"(r[1]), "=r"(r[2]), "=r"(r[3]) : "r"(addr));
}
__device__ __forceinline__ void mma16816h(float* c, const uint32_t* a, const uint32_t* b) {
    asm volatile(
        "mma.sync.aligned.m16n8k16.row.col.f32.f16.f16.f32 "
        "{%0,%1,%2,%3}, {%4,%5,%6,%7}, {%8,%9}, {%0,%1,%2,%3};"
        : "+f"(c[0]), "+f"(c[1]), "+f"(c[2]), "+f"(c[3])
        : "r"(a[0]), "r"(a[1]), "r"(a[2]), "r"(a[3]), "r"(b[0]), "r"(b[1]));
}
__device__ __forceinline__ float ex2f(float x) {
    float y; asm("ex2.approx.f32 %0, %1;" : "=f"(y) : "f"(x)); return y;
}
#define CP16(dst, src) asm volatile("cp.async.cg.shared.global [%0], [%1], 16;" :: "r"(dst), "l"(src))
#define CP_COMMIT()    asm volatile("cp.async.commit_group;" ::: "memory")
#define CP_WAIT1()     asm volatile("cp.async.wait_group 1;" ::: "memory")
#define CP_WAIT0()     asm volatile("cp.async.wait_group 0;" ::: "memory")

#define KC 64
#define RSTR 72
#define TILE_B (128 * RSTR * 2)          // 18432 B per 128-row fp16 tile
#define STAGE2_B (2 * TILE_B)            // A, B = 36864 B (qkv single-pass)
#define DSTR 132

__device__ __forceinline__ uint32_t packh2(float x, float y) {
    __half2 hh = __floats2half2_rn(x, y);
    return *(uint32_t*)&hh;
}

// ---------------- kernel 1: time projections (parallelized) ----------------
__global__ void __launch_bounds__(128) time_proj(
    const float* __restrict__ time_emb,
    const float* __restrict__ Wqt, const float* __restrict__ bqt,
    const float* __restrict__ Wkt, const float* __restrict__ bkt,
    const float* __restrict__ Wvt, const float* __restrict__ bvt)
{
    const int b = blockIdx.y;
    const int n = blockIdx.x * 128 + threadIdx.x;
    __shared__ float te[Tt];
    for (int i = threadIdx.x; i < Tt; i += 128)
        te[i] = time_emb[b * Tt + i];
    __syncthreads();
    float aq = 0.f, ak = 0.f, av = 0.f;
    for (int t = 0; t < Tt; t++) {
        float x = te[t];
        aq += x * Wqt[t * Dm + n];
        ak += x * Wkt[t * Dm + n];
        av += x * Wvt[t * Dm + n];
    }
    g_T[0][b][n] = aq + bqt[n];
    g_T[1][b][n] = ak + bkt[n];
    g_T[2][b][n] = av + bvt[n];
}

// ---------------- kernel 2: fused preps (patches | er | wt) ----------------
// blocks [0,6144): patches; [6144,6208): er; [6208,7936): wt
__global__ void __launch_bounds__(256) prep_all(
    const float* __restrict__ patches, const float* __restrict__ Er,
    const float* __restrict__ Wq, const float* __restrict__ Wk,
    const float* __restrict__ Wv)
{
    const int bid = blockIdx.x;
    if (bid < 6144) {
        size_t i = (size_t)bid * 256 + threadIdx.x;
        float4 v = ((const float4*)patches)[i];
        uint32_t* H = (uint32_t*)g_P16;
        H[2 * i] = packh2(v.x, v.y);
        H[2 * i + 1] = packh2(v.z, v.w);
    } else if (bid < 6208) {
        size_t i = (size_t)(bid - 6144) * 256 + threadIdx.x;
        float4 v = ((const float4*)Er)[i];
        uint32_t* E = (uint32_t*)&g_Er16[0][0];
        E[2 * i] = packh2(v.x, v.y);
        E[2 * i + 1] = packh2(v.z, v.w);
    } else {
        const int w = bid - 6208;
        const int z = w / 576;
        const int rem = w % 576;
        const int n0 = (rem % 24) * 32, k0 = (rem / 24) * 32;
        const float* __restrict__ W = (z == 0) ? Wq : (z == 1 ? Wk : Wv);
        __shared__ float s[32][33];
        const int tx = threadIdx.x & 31, ty = threadIdx.x >> 5;
        #pragma unroll
        for (int i = 0; i < 4; i++)
            s[ty + 8 * i][tx] = W[(size_t)(k0 + ty + 8 * i) * Dm + n0 + tx];
        __syncthreads();
        #pragma unroll
        for (int i = 0; i < 4; i++) {
            int n = n0 + ty + 8 * i, k = k0 + tx;
            g_WT16[z][n][k] = __float2half_rn(s[tx][ty + 8 * i]);
        }
    }
}

// ---------------- microkernel: one Kc=64 chunk, single-pass fp16 -----------
__device__ __forceinline__ void mma_chunk1(uint32_t stage_base, int wm, int wn,
                                           int lane, float c[4][4][4])
{
    const uint32_t aRow = (uint32_t)(wm * 64 + (lane & 15));
    const uint32_t aColBase = (uint32_t)((lane >> 4) * 8);
    const uint32_t bRow = (uint32_t)(wn * 32 + ((lane >> 3) & 1) * 8 + (lane & 7));
    const uint32_t sA = stage_base;
    const uint32_t sB = stage_base + TILE_B;

    #pragma unroll
    for (int ks = 0; ks < 4; ks++) {
        const uint32_t kcol = (uint32_t)(ks * 16) + aColBase;
        uint32_t aa[4][4], bb[4][2];
        #pragma unroll
        for (int mt = 0; mt < 4; mt++) {
            uint32_t off = ((aRow + mt * 16) * RSTR + kcol) * 2;
            ldmx4(aa[mt], sA + off);
        }
        #pragma unroll
        for (int nt2 = 0; nt2 < 2; nt2++) {
            uint32_t off = ((bRow + nt2 * 16) * RSTR + kcol) * 2;
            uint32_t t[4];
            ldmx4(t, sB + off);
            bb[nt2 * 2][0] = t[0]; bb[nt2 * 2][1] = t[2];
            bb[nt2 * 2 + 1][0] = t[1]; bb[nt2 * 2 + 1][1] = t[3];
        }
        #pragma unroll
        for (int mt = 0; mt < 4; mt++)
            #pragma unroll
            for (int nt = 0; nt < 4; nt++)
                mma16816h(c[mt][nt], aa[mt], bb[nt]);
    }
}

// ---------------- kernel 3: QKV via mma.sync fp16 (3-stage, 2 CTA/SM) ------
__global__ void __launch_bounds__(256, 2) qkv_mma(
    const float* __restrict__ bq, const float* __restrict__ bk,
    const float* __restrict__ bv)
{
    extern __shared__ char sm[];
    const uint32_t smb = smem_u32(sm);
    const int z = blockIdx.z;
    const int n0 = blockIdx.x * 128, m0 = blockIdx.y * 128;
    const int tid = threadIdx.x;
    const int warp = tid >> 5, lane = tid & 31;
    const int wm = warp & 1, wn = warp >> 1;

    auto load_stage = [&](int chunk, int s) {
        const uint32_t st = smb + (uint32_t)s * STAGE2_B;
        const int k0 = chunk * KC;
        #pragma unroll
        for (int it = 0; it < 4; it++) {
            int i = tid + it * 256;
            int r = i >> 3, cc = i & 7;
            uint32_t doff = (uint32_t)(r * RSTR + cc * 8) * 2;
            CP16(st + doff, g_P16 + (size_t)(m0 + r) * Dm + k0 + cc * 8);
            CP16(st + TILE_B + doff, &g_WT16[z][n0 + r][k0 + cc * 8]);
        }
        CP_COMMIT();
    };

    float c[4][4][4] = {};

    load_stage(0, 0);
    load_stage(1, 1);
    for (int ch = 0; ch < 12; ch++) {
        if (ch < 10) CP_WAIT1(); else CP_WAIT0();
        __syncthreads();
        if (ch + 2 < 12) load_stage(ch + 2, (ch + 2) % 3);
        mma_chunk1(smb + (uint32_t)(ch % 3) * STAGE2_B, wm, wn, lane, c);
    }

    const float* bias = (z == 0) ? bq : (z == 1 ? bk : bv);
    const int lrow = lane >> 2, lcol = (lane & 3) * 2;
    #pragma unroll
    for (int mt = 0; mt < 4; mt++) {
        #pragma unroll
        for (int nt = 0; nt < 4; nt++) {
            const int col = n0 + wn * 32 + nt * 8 + lcol;
            const float bx = bias[col], by = bias[col + 1];
            #pragma unroll
            for (int hf = 0; hf < 2; hf++) {
                const int row = m0 + wm * 64 + mt * 16 + lrow + hf * 8;
                const int b = row >> 10;
                const float v0 = c[mt][nt][hf * 2 + 0] + bx;
                const float v1 = c[mt][nt][hf * 2 + 1] + by;
                const float t0 = g_T[z][b][col];
                const float t1 = g_T[z][b][col + 1];
                const size_t o = (size_t)row * Dm + col;
                if (z == 0) {
                    *(uint32_t*)&g_Q16[o] = packh2((v0 + t0) * SCALE_L2E,
                                                   (v1 + t1) * SCALE_L2E);
                    *(uint32_t*)&g_QS16[o] = packh2(v0 * SCALE_L2E, v1 * SCALE_L2E);
                } else if (z == 1) {
                    *(uint32_t*)&g_K16[o] = packh2(v0 + t0, v1 + t1);
                } else {
                    *(uint32_t*)&g_V16[o] = packh2(v0 + t0, v1 + t1);
                }
            }
        }
    }
}

// ---------------- kernel 4: fused flash attention + rel-bias (fp16) --------
// 256 threads (8 warps), 2 CTAs/SM. Warp = wp (16 q rows) x wh (32-col k-half).
// Diagonal bias layout, log2-domain softmax (scale folded into Q/QS).
// D strips: strip s == blockIdx.x contains e=1 -> mixed path (per-row shift,
// e==1 zeroing). All other strips have uniform shift p = (s > bx) and use the
// transposed formulation O[e][q] = Er_strip x QS(rows q+p): 16 MMAs, 12 ldsm.
#define aQ    0u            /* 64x72 fp16 = 9216 */
#define aQS   9216u         /* 80x72 fp16 = 11520 */
#define aKV   20736u        /* stage: K16 | V16 each 9216 = 18432; x2 */
#define aEr   57600u        /* 192x72 fp16 = 27648 */
#define aD    85248u        /* 64x132 fp16 = 16896 */
#define aRed  102408u       /* sM 128 f32 + sL 128 f32 */
#define ATTN_SMEM 103432
#define OSTR 68

__global__ void __launch_bounds__(256, 2) attn_mma(float* __restrict__ out)
{
    extern __shared__ char sm[];
    const uint32_t smb = smem_u32(sm);
    const int bx = blockIdx.x;
    const int q0 = bx * 64;
    const int h = blockIdx.y, b = blockIdx.z;
    const int tid = threadIdx.x, warp = tid >> 5, lane = tid & 31;
    const int wp = warp & 3, wh = warp >> 2;
    __half* Dd = (__half*)(sm + aD);
    float* sM = (float*)(sm + aRed);
    float* sL = sM + 128;

    auto load_kv = [&](int kt, int s) {
        const uint32_t st = smb + aKV + (uint32_t)s * 18432u;
        const size_t krow0 = ((size_t)(b * Sq + kt * 64)) * Dm + h * HDm;
        #pragma unroll
        for (int it = 0; it < 2; it++) {
            int i = tid + it * 256;
            int r = i >> 3, cc = i & 7;
            uint32_t doff = (uint32_t)(r * RSTR + cc * 8) * 2;
            size_t src = krow0 + (size_t)r * Dm + cc * 8;
            CP16(st + doff, g_K16 + src);
            CP16(st + 9216u + doff, g_V16 + src);
        }
    };
    auto load_er = [&](int s) {
        const int estart = s * 64 - q0;
        const int slot = ((s + 3) % 3) * 64;
        #pragma unroll
        for (int it = 0; it < 2; it++) {
            int i = tid + it * 256;
            int r = i >> 3, cc = i & 7;
            int e = estart + r;
            int t = (e <= 0) ? (Sq - 1 + e) : (e - 2);
            if (t < 0) t = 0; if (t > Sq - 1) t = Sq - 1;
            uint32_t doff = (uint32_t)((slot + r) * RSTR + cc * 8) * 2;
            CP16(smb + aEr + doff, &g_Er16[t][cc * 8]);
        }
    };
    // mixed strip (contains e=1): old formulation, per-row shift + zeroing
    auto do_dstrip_m = [&](int s) {
        const int base = s * 64 - q0;
        const uint32_t erow0 = (uint32_t)(((s + 3) % 3) * 64);
        const int par = warp & 1;
        uint32_t eb[4][2];
        const uint32_t nrow = erow0 +
            (uint32_t)((warp & 6) * 8 + ((lane >> 3) & 1) * 8 + (lane & 7));
        #pragma unroll
        for (int ks = 0; ks < 4; ks++) {
            uint32_t addr = smb + aEr +
                (nrow * RSTR + (uint32_t)(ks * 16 + (lane >> 4) * 8)) * 2;
            uint32_t t4[4];
            ldmx4(t4, addr);
            eb[ks][0] = t4[par]; eb[ks][1] = t4[2 + par];
        }
        const int e0 = base + warp * 8 + (lane & 3) * 2;  // even
        #pragma unroll
        for (int mt = 0; mt < 5; mt++) {
            uint32_t sa[4][4];
            const uint32_t arow = (uint32_t)(mt * 16 + (lane & 15));
            #pragma unroll
            for (int ks = 0; ks < 4; ks++) {
                uint32_t addr = smb + aQS +
                    (arow * RSTR + (uint32_t)(ks * 16 + (lane >> 4) * 8)) * 2;
                ldmx4(sa[ks], addr);
            }
            float cc4[4] = {};
            #pragma unroll
            for (int ks = 0; ks < 4; ks++)
                mma16816h(cc4, sa[ks], eb[ks]);
            const int p = (e0 >= 2) ? 1 : 0;
            #pragma unroll
            for (int rr = 0; rr < 2; rr++) {
                const int r = mt * 16 + (lane >> 2) + rr * 8;
                const int q_dst = r - p;
                if (q_dst >= 0 && q_dst < 64) {
                    const int j0 = (e0 + q_dst) & 127;
                    const int j1 = (e0 + 1 + q_dst) & 127;
                    Dd[q_dst * DSTR + j0] = __float2half_rn(cc4[rr * 2]);
                    Dd[q_dst * DSTR + j1] =
                        (e0 + 1 == 1) ? __float2half_rn(0.f)
                                      : __float2half_rn(cc4[rr * 2 + 1]);
                }
            }
        }
    };
    // uniform strip: O[e][q] = Er_strip(64 rows) x QS(rows q+p); store direct
    auto do_dstrip_u = [&](int s, int p) {
        const int estart = s * 64 - q0;
        const uint32_t erow0 = (uint32_t)(((s + 3) % 3) * 64);
        uint32_t ea[4][4];
        {
            const uint32_t arow = erow0 + (uint32_t)(wp * 16 + (lane & 15));
            #pragma unroll
            for (int ks = 0; ks < 4; ks++) {
                uint32_t addr = smb + aEr +
                    (arow * RSTR + (uint32_t)(ks * 16 + (lane >> 4) * 8)) * 2;
                ldmx4(ea[ks], addr);
            }
        }
        float c4[4][4] = {};
        #pragma unroll
        for (int ks = 0; ks < 4; ks++) {
            uint32_t bb[4][2];
            #pragma unroll
            for (int pp = 0; pp < 2; pp++) {
                uint32_t nrow = (uint32_t)(p + wh * 32 + pp * 16 +
                                ((lane >> 3) & 1) * 8 + (lane & 7));
                uint32_t addr = smb + aQS +
                    (nrow * RSTR + (uint32_t)(ks * 16 + (lane >> 4) * 8)) * 2;
                uint32_t t4[4];
                ldmx4(t4, addr);
                bb[pp * 2][0] = t4[0]; bb[pp * 2][1] = t4[2];
                bb[pp * 2 + 1][0] = t4[1]; bb[pp * 2 + 1][1] = t4[3];
            }
            #pragma unroll
            for (int nt = 0; nt < 4; nt++)
                mma16816h(c4[nt], ea[ks], bb[nt]);
        }
        #pragma unroll
        for (int nt = 0; nt < 4; nt++) {
            #pragma unroll
            for (int hf = 0; hf < 2; hf++) {
                const int e_abs = estart + wp * 16 + (lane >> 2) + hf * 8;
                const int qb = wh * 32 + nt * 8 + (lane & 3) * 2;
                Dd[qb * DSTR + ((e_abs + qb) & 127)] =
                    __float2half_rn(c4[nt][hf * 2]);
                Dd[(qb + 1) * DSTR + ((e_abs + qb + 1) & 127)] =
                    __float2half_rn(c4[nt][hf * 2 + 1]);
            }
        }
    };
    auto dstrip = [&](int s) {
        if (s == bx) do_dstrip_m(s);
        else do_dstrip_u(s, (s > bx) ? 1 : 0);
    };

    // ---- prologue loads: G0 = {Q, QS, er(-1,0,1), kv0}, G1 = {kv1} --------
    {
        const size_t qrow0 = ((size_t)(b * Sq + q0)) * Dm + h * HDm;
        #pragma unroll
        for (int it = 0; it < 2; it++) {
            int i = tid + it * 256;
            int r = i >> 3, cc = i & 7;
            uint32_t doff = (uint32_t)(r * RSTR + cc * 8) * 2;
            CP16(smb + aQ + doff, g_Q16 + qrow0 + (size_t)r * Dm + cc * 8);
        }
        #pragma unroll
        for (int it = 0; it < 3; it++) {
            int i = tid + it * 256;
            if (i < 640) {
                int r = i >> 3, cc = i & 7;
                int rr = q0 + r; if (rr > Sq - 1) rr = Sq - 1;
                uint32_t doff = (uint32_t)(r * RSTR + cc * 8) * 2;
                CP16(smb + aQS + doff,
                     g_QS16 + ((size_t)(b * Sq + rr)) * Dm + h * HDm + cc * 8);
            }
        }
        load_er(-1); load_er(0); load_er(1);
        load_kv(0, 0);
        CP_COMMIT();                 // G0
        load_kv(1, 1);
        CP_COMMIT();                 // G1
    }

    CP_WAIT1();
    __syncthreads();                 // G0 visible (Q, QS, er(-1,0,1), kv0)

    // ---- hoist Q fragments (loop-invariant) ----
    uint32_t qa[4][4];
    {
        const uint32_t arow = (uint32_t)(wp * 16 + (lane & 15));
        #pragma unroll
        for (int ks = 0; ks < 4; ks++) {
            uint32_t addr = smb + aQ +
                (arow * RSTR + (uint32_t)(ks * 16 + (lane >> 4) * 8)) * 2;
            ldmx4(qa[ks], addr);
        }
    }

    // ---- prologue D strips {-1, 0} ----
    dstrip(-1);
    dstrip(0);
    __syncthreads();                 // Dd + all prologue dstrip reads done

    float m_[2] = {-1e30f, -1e30f}, l_[2] = {0.f, 0.f};
    float co[8][4] = {};
    const int row16 = (lane >> 2);

    for (int kt = 0; kt < 16; kt++) {
        const int s = kt & 1;
        const int d0 = kt * 64 - q0;
        if (kt > 0) { CP_WAIT1(); __syncthreads(); }  // KV(kt), Er(kt+1), Dd(kt)

        // ---- QK^T: fp16 1-pass, 16 q rows x 32 k cols per warp ----
        float c[4][4] = {};
        {
            const uint32_t stK = smb + aKV + (uint32_t)s * 18432u;
            #pragma unroll
            for (int ks = 0; ks < 4; ks++) {
                uint32_t bh[4][2];
                #pragma unroll
                for (int pp = 0; pp < 2; pp++) {
                    uint32_t nrow = (uint32_t)(wh * 32 + pp * 16 +
                                    ((lane >> 3) & 1) * 8 + (lane & 7));
                    uint32_t addr = stK +
                        (nrow * RSTR + (uint32_t)(ks * 16 + (lane >> 4) * 8)) * 2;
                    uint32_t t4[4];
                    ldmx4(t4, addr);
                    bh[pp * 2][0] = t4[0]; bh[pp * 2][1] = t4[2];
                    bh[pp * 2 + 1][0] = t4[1]; bh[pp * 2 + 1][1] = t4[3];
                }
                #pragma unroll
                for (int nt = 0; nt < 4; nt++)
                    mma16816h(c[nt], qa[ks], bh[nt]);
            }
        }

        // ---- bias add (diagonal; ready via top sync) + log2 softmax ----
        float mloc[2] = {-1e30f, -1e30f};
        #pragma unroll
        for (int hf = 0; hf < 2; hf++) {
            const int q_loc = wp * 16 + row16 + hf * 8;
            const uint32_t rbase = (uint32_t)(q_loc * DSTR);
            #pragma unroll
            for (int nt = 0; nt < 4; nt++) {
                const int col = wh * 32 + nt * 8 + (lane & 3) * 2;
                const int idx = (d0 + col) & 127;        // even -> aligned
                __half2 b2 = *(__half2*)&Dd[rbase + idx];
                float2 bf = __half22float2(b2);
                float sv0 = c[nt][hf * 2 + 0] + bf.x;
                float sv1 = c[nt][hf * 2 + 1] + bf.y;
                c[nt][hf * 2 + 0] = sv0;
                c[nt][hf * 2 + 1] = sv1;
                mloc[hf] = fmaxf(mloc[hf], fmaxf(sv0, sv1));
            }
        }
        float corr[2], psum[2] = {0.f, 0.f};
        #pragma unroll
        for (int hf = 0; hf < 2; hf++) {
            mloc[hf] = fmaxf(mloc[hf], __shfl_xor_sync(0xffffffffu, mloc[hf], 1));
            mloc[hf] = fmaxf(mloc[hf], __shfl_xor_sync(0xffffffffu, mloc[hf], 2));
            float mn = fmaxf(m_[hf], mloc[hf]);
            corr[hf] = ex2f(m_[hf] - mn);
            m_[hf] = mn;
        }
        #pragma unroll
        for (int nt = 0; nt < 4; nt++) {
            #pragma unroll
            for (int k4 = 0; k4 < 4; k4++) {
                const int hf = k4 >> 1;
                float p = ex2f(c[nt][k4] - m_[hf]);
                c[nt][k4] = p;
                psum[hf] += p;
            }
        }
        #pragma unroll
        for (int hf = 0; hf < 2; hf++) {
            psum[hf] += __shfl_xor_sync(0xffffffffu, psum[hf], 1);
            psum[hf] += __shfl_xor_sync(0xffffffffu, psum[hf], 2);
            l_[hf] = l_[hf] * corr[hf] + psum[hf];
        }
        #pragma unroll
        for (int nt = 0; nt < 8; nt++) {
            co[nt][0] *= corr[0]; co[nt][1] *= corr[0];
            co[nt][2] *= corr[1]; co[nt][3] *= corr[1];
        }

        // ---- PV: Ph(fp16) x V(fp16), 1 pass ----
        {
            const uint32_t stV = smb + aKV + (uint32_t)s * 18432u + 9216u;
            #pragma unroll
            for (int ktk = 0; ktk < 2; ktk++) {
                uint32_t pha[4];
                #pragma unroll
                for (int sub = 0; sub < 2; sub++)
                    #pragma unroll
                    for (int h2 = 0; h2 < 2; h2++)
                        pha[h2 + sub * 2] = packh2(c[2 * ktk + sub][h2 * 2],
                                                   c[2 * ktk + sub][h2 * 2 + 1]);
                uint32_t vb[8][2];
                #pragma unroll
                for (int pp = 0; pp < 4; pp++) {
                    uint32_t krow = (uint32_t)(wh * 32 + ktk * 16 +
                                   (lane & 7) + ((lane >> 3) & 1) * 8);
                    uint32_t ncol = (uint32_t)(pp * 16 + (lane >> 4) * 8);
                    uint32_t addr = stV + (krow * RSTR + ncol) * 2;
                    uint32_t t4[4];
                    ldmx4t(t4, addr);
                    vb[pp * 2][0] = t4[0]; vb[pp * 2][1] = t4[1];
                    vb[pp * 2 + 1][0] = t4[2]; vb[pp * 2 + 1][1] = t4[3];
                }
                #pragma unroll
                for (int nt = 0; nt < 8; nt++)
                    mma16816h(co[nt], pha, vb[nt]);
            }
        }

        __syncthreads();   // ALL bias(kt)+PV(kt) reads done before dstrip/loads

        // ---- D strip kt+1 (after sync: cannot clobber in-flight reads) ----
        if (kt + 1 <= 15) dstrip(kt + 1);

        if (kt + 2 < 16) load_kv(kt + 2, s);
        if (kt + 2 == 2) load_er(2);    // slot 2 free after prologue dstrips
        if (kt + 3 <= 15) load_er(kt + 3);
        CP_COMMIT();
    }

    // ---- merge the two k-half softmax states, write out ----
    if ((lane & 3) == 0) {
        #pragma unroll
        for (int hf = 0; hf < 2; hf++) {
            sM[wh * 64 + wp * 16 + row16 + hf * 8] = m_[hf];
            sL[wh * 64 + wp * 16 + row16 + hf * 8] = l_[hf];
        }
    }
    __syncthreads();
    float myc[2], inv[2];
    #pragma unroll
    for (int hf = 0; hf < 2; hf++) {
        const int rowi = wp * 16 + row16 + hf * 8;
        float mo = sM[(wh ^ 1) * 64 + rowi];
        float lo2 = sL[(wh ^ 1) * 64 + rowi];
        float mstar = fmaxf(m_[hf], mo);
        myc[hf] = ex2f(m_[hf] - mstar);
        float otc = ex2f(mo - mstar);
        inv[hf] = 1.0f / (l_[hf] * myc[hf] + lo2 * otc);
    }
    __syncthreads();
    float* sOut = (float*)(sm + aKV);
    if (wh == 1) {
        #pragma unroll
        for (int hf = 0; hf < 2; hf++) {
            const int row = wp * 16 + row16 + hf * 8;
            #pragma unroll
            for (int nt = 0; nt < 8; nt++) {
                const int col = nt * 8 + (lane & 3) * 2;
                *(float2*)&sOut[row * OSTR + col] =
                    make_float2(co[nt][hf * 2] * myc[hf],
                                co[nt][hf * 2 + 1] * myc[hf]);
            }
        }
    }
    __syncthreads();
    if (wh == 0) {
        #pragma unroll
        for (int hf = 0; hf < 2; hf++) {
            const int row = wp * 16 + row16 + hf * 8;
            const size_t ob = ((size_t)(b * Sq + q0 + row)) * Dm + h * HDm;
            #pragma unroll
            for (int nt = 0; nt < 8; nt++) {
                const int col = nt * 8 + (lane & 3) * 2;
                float2 pr = *(float2*)&sOut[row * OSTR + col];
                *(float2*)&out[ob + col] =
                    make_float2((co[nt][hf * 2] * myc[hf] + pr.x) * inv[hf],
                                (co[nt][hf * 2 + 1] * myc[hf] + pr.y) * inv[hf]);
            }
        }
    }
}

// ---------------- launch ----------------------------------------------------
extern "C" void kernel_launch(void* const* d_in, const int* in_sizes, int n_in,
                              void* d_out, int out_size)
{
    (void)in_sizes; (void)n_in; (void)out_size;
    const float* patches  = (const float*)d_in[0];
    const float* time_emb = (const float*)d_in[1];
    const float* Wqs = (const float*)d_in[2];
    const float* bqs = (const float*)d_in[3];
    const float* Wks = (const float*)d_in[4];
    const float* bks = (const float*)d_in[5];
    const float* Wvs = (const float*)d_in[6];
    const float* bvs = (const float*)d_in[7];
    const float* Wqt = (const float*)d_in[8];
    const float* bqt = (const float*)d_in[9];
    const float* Wkt = (const float*)d_in[10];
    const float* bkt = (const float*)d_in[11];
    const float* Wvt = (const float*)d_in[12];
    const float* bvt = (const float*)d_in[13];
    const float* Er  = (const float*)d_in[14];
    float* out = (float*)d_out;

    time_proj<<<dim3(Dm / 128, Bb), 128>>>(time_emb, Wqt, bqt, Wkt, bkt, Wvt, bvt);
    prep_all<<<7936, 256>>>(patches, Er, Wqs, Wks, Wvs);

    const int qkv_smem = 3 * STAGE2_B;  // 110592 -> 2 CTAs/SM
    cudaFuncSetAttribute(qkv_mma, cudaFuncAttributeMaxDynamicSharedMemorySize, qkv_smem);
    qkv_mma<<<dim3(Dm / 128, (Bb * Sq) / 128, 3), 256, qkv_smem>>>(bqs, bks, bvs);

    cudaFuncSetAttribute(attn_mma, cudaFuncAttributeMaxDynamicSharedMemorySize, ATTN_SMEM);
    attn_mma<<<dim3(Sq / 64, Hh, Bb), 256, ATTN_SMEM>>>(out);
}